// round 6
// baseline (speedup 1.0000x reference)
#include <cuda_runtime.h>
#include <math.h>

// ---------------- problem constants ----------------
#define BB 8
#define TT 1024
#define FF 32
#define EE 16
#define DD 512
#define LL 6
#define HH 8
#define HS 64
#define DFF 2048
#define NT (BB*TT)          // 8192 token rows
#define QKVN (3*DD)         // 1536

// ---------------- scratch (device globals; no allocs allowed) ----------------
__device__ float g_x[NT*DD];
__device__ float g_xn[NT*DD];
__device__ float g_qkv[NT*QKVN];
__device__ float g_ao[NT*DD];
__device__ float g_h1[NT*DFF];
__device__ float g_wt[DD*QKVN];
__device__ float g_scores[NT];
__device__ float g_summary[BB*DD];

// ---------------- reductions ----------------
__device__ __forceinline__ float warp_sum(float v){
#pragma unroll
    for (int o=16;o;o>>=1) v += __shfl_xor_sync(0xffffffffu, v, o);
    return v;
}
__device__ __forceinline__ float warp_max(float v){
#pragma unroll
    for (int o=16;o;o>>=1) v = fmaxf(v, __shfl_xor_sync(0xffffffffu, v, o));
    return v;
}
__device__ float block_sum(float v, float* sh){
    int lane = threadIdx.x & 31, w = threadIdx.x >> 5;
    v = warp_sum(v);
    if (lane==0) sh[w] = v;
    __syncthreads();
    int nw = (blockDim.x + 31) >> 5;
    float r = (threadIdx.x < nw) ? sh[threadIdx.x] : 0.f;
    r = warp_sum(r);
    if (threadIdx.x==0) sh[0] = r;
    __syncthreads();
    r = sh[0];
    __syncthreads();
    return r;
}
__device__ float block_max(float v, float* sh){
    int lane = threadIdx.x & 31, w = threadIdx.x >> 5;
    v = warp_max(v);
    if (lane==0) sh[w] = v;
    __syncthreads();
    int nw = (blockDim.x + 31) >> 5;
    float r = (threadIdx.x < nw) ? sh[threadIdx.x] : -3.0e38f;
    r = warp_max(r);
    if (threadIdx.x==0) sh[0] = r;
    __syncthreads();
    r = sh[0];
    __syncthreads();
    return r;
}

// ---------------- embedding + positional encoding ----------------
__global__ void embed_kernel(const int* __restrict__ code, const float* __restrict__ emb,
                             float* __restrict__ x){
    int idx = blockIdx.x*blockDim.x + threadIdx.x;
    if (idx >= NT*DD) return;
    int d  = idx % DD;
    int bt = idx / DD;
    int t  = bt % TT;
    int f  = d / EE, e = d % EE;
    int c  = code[bt*FF + f];
    float i2  = (float)((d >> 1) << 1);
    float div = __expf(i2 * (-9.210340371976184f / (float)DD));   // -ln(10000)/D
    float ang = (float)t * div;
    float pe  = (d & 1) ? cosf(ang) : sinf(ang);
    x[idx] = emb[c*EE + e] + pe;
}

// ---------------- LayerNorm (one block per row) ----------------
__global__ void ln_kernel(const float* __restrict__ x, const float* __restrict__ g,
                          const float* __restrict__ b, float* __restrict__ y){
    __shared__ float sh[32];
    int row = blockIdx.x;
    int tid = threadIdx.x;                     // 256 threads, D=512
    const float* xr = x + (size_t)row*DD;
    float v0 = xr[tid], v1 = xr[tid+256];
    float mean = block_sum(v0+v1, sh) * (1.0f/DD);
    float d0 = v0-mean, d1 = v1-mean;
    float var = block_sum(d0*d0 + d1*d1, sh) * (1.0f/DD);
    float inv = rsqrtf(var + 1e-5f);
    y[(size_t)row*DD + tid]       = d0*inv*g[tid]     + b[tid];
    y[(size_t)row*DD + tid + 256] = d1*inv*g[tid+256] + b[tid+256];
}

// ---------------- pack Wq/Wk/Wv[l] into (D, 1536) column layout ----------------
__global__ void wqkv_t_kernel(const float* __restrict__ Wq, const float* __restrict__ Wk,
                              const float* __restrict__ Wv, float* __restrict__ Wt, int l){
    int idx = blockIdx.x*blockDim.x + threadIdx.x;
    if (idx >= DD*QKVN) return;
    int j = idx % QKVN;
    int d = idx / QKVN;
    int sel = j >> 9;          // /512
    int h   = (j >> 6) & 7;
    int e   = j & 63;
    const float* W = (sel==0) ? Wq : (sel==1) ? Wk : Wv;
    Wt[idx] = W[(((size_t)l*HH + h)*DD + d)*HS + e];
}

// ---------------- SGEMM: C[M,N] = A[M,K] @ B[K,N], fused epilogue ----------------
// 128x128 tile, BK=16, 8x8 microtile, double-buffered smem.
// Requires M%128==0, N%128==0, K%16==0 (true for all call sites).
// epi bit0: +bias[col]; bit1: exact GELU; bit2: +res[row*N+col]
#define BM 128
#define BN 128
#define BK 16
__global__ void __launch_bounds__(256, 2)
sgemm_kernel(const float* __restrict__ A, const float* __restrict__ B,
             float* __restrict__ C, const float* __restrict__ bias,
             const float* __restrict__ res, int M, int N, int K, int epi){
    __shared__ float As[2][BK][BM+4];
    __shared__ float Bs[2][BK][BN];
    int tid = threadIdx.x;
    int row0 = blockIdx.y * BM, col0 = blockIdx.x * BN;
    int tx = tid & 15, ty = tid >> 4;

    // A tile cooperative load: 128 rows x 16 k = 512 float4, 2 per thread.
    int arow = tid >> 2;              // 0..63 (second load: +64)
    int akq  = (tid & 3) << 2;        // k offset 0,4,8,12
    // B tile cooperative load: 16 rows x 128 cols = 512 float4, 2 per thread.
    int brow = tid >> 5;              // 0..7 (second load: +8)
    int bcol = (tid & 31) << 2;

    const float* Ar0 = A + (size_t)(row0 + arow     )*K + akq;
    const float* Ar1 = A + (size_t)(row0 + arow + 64)*K + akq;
    const float* Br0 = B + (size_t)(brow    )*N + col0 + bcol;
    const float* Br1 = B + (size_t)(brow + 8)*N + col0 + bcol;

    // prologue: tile 0 -> buffer 0
    float4 av0 = *(const float4*)Ar0;
    float4 av1 = *(const float4*)Ar1;
    float4 bv0 = *(const float4*)Br0;
    float4 bv1 = *(const float4*)Br1;
    As[0][akq+0][arow]=av0.x; As[0][akq+1][arow]=av0.y;
    As[0][akq+2][arow]=av0.z; As[0][akq+3][arow]=av0.w;
    As[0][akq+0][arow+64]=av1.x; As[0][akq+1][arow+64]=av1.y;
    As[0][akq+2][arow+64]=av1.z; As[0][akq+3][arow+64]=av1.w;
    *(float4*)&Bs[0][brow  ][bcol] = bv0;
    *(float4*)&Bs[0][brow+8][bcol] = bv1;
    __syncthreads();

    float acc[8][8] = {};
    int buf = 0;
    for (int k0 = 0; k0 < K; k0 += BK){
        bool has_next = (k0 + BK) < K;
        if (has_next){
            av0 = *(const float4*)(Ar0 + k0 + BK);
            av1 = *(const float4*)(Ar1 + k0 + BK);
            bv0 = *(const float4*)(Br0 + (size_t)(k0 + BK)*N);
            bv1 = *(const float4*)(Br1 + (size_t)(k0 + BK)*N);
        }
#pragma unroll
        for (int kk = 0; kk < BK; kk++){
            float a[8], b[8];
            *(float4*)(a  ) = *(const float4*)&As[buf][kk][(ty<<2)     ];
            *(float4*)(a+4) = *(const float4*)&As[buf][kk][(ty<<2) + 64];
            *(float4*)(b  ) = *(const float4*)&Bs[buf][kk][(tx<<2)     ];
            *(float4*)(b+4) = *(const float4*)&Bs[buf][kk][(tx<<2) + 64];
#pragma unroll
            for (int i=0;i<8;i++)
#pragma unroll
                for (int j=0;j<8;j++)
                    acc[i][j] += a[i]*b[j];
        }
        if (has_next){
            int nb = buf ^ 1;
            As[nb][akq+0][arow]=av0.x; As[nb][akq+1][arow]=av0.y;
            As[nb][akq+2][arow]=av0.z; As[nb][akq+3][arow]=av0.w;
            As[nb][akq+0][arow+64]=av1.x; As[nb][akq+1][arow+64]=av1.y;
            As[nb][akq+2][arow+64]=av1.z; As[nb][akq+3][arow+64]=av1.w;
            *(float4*)&Bs[nb][brow  ][bcol] = bv0;
            *(float4*)&Bs[nb][brow+8][bcol] = bv1;
            __syncthreads();
            buf = nb;
        }
    }

    // epilogue: 2x2 halves of the 8x8 microtile, float4 stores
#pragma unroll
    for (int ih = 0; ih < 2; ih++){
#pragma unroll
        for (int i = 0; i < 4; i++){
            int r = row0 + ih*64 + (ty<<2) + i;
#pragma unroll
            for (int jh = 0; jh < 2; jh++){
                int c = col0 + jh*64 + (tx<<2);
                float vv[4];
#pragma unroll
                for (int j = 0; j < 4; j++){
                    float v = acc[ih*4+i][jh*4+j];
                    if (epi & 1) v += bias[c + j];
                    if (epi & 2) v = 0.5f*v*(1.0f + erff(v*0.70710678118654752f));
                    vv[j] = v;
                }
                if (epi & 4){
                    float4 rv = *(const float4*)&res[(size_t)r*N + c];
                    vv[0]+=rv.x; vv[1]+=rv.y; vv[2]+=rv.z; vv[3]+=rv.w;
                }
                *(float4*)&C[(size_t)r*N + c] = make_float4(vv[0],vv[1],vv[2],vv[3]);
            }
        }
    }
}

// ---------------- flash attention: CTA per (b, h, 64-query tile) ----------------
// dynamic smem layout: Qt[64*68] | KPt[64*68] (K tile, reused for P) | Vs[64*64]
#define ATT_SMEM ((64*68*2 + 64*64)*4)
__global__ void __launch_bounds__(256)
attn_kernel(const float* __restrict__ qkv, const int* __restrict__ lengths,
            float* __restrict__ ao){
    extern __shared__ float sm[];
    float* Qt  = sm;
    float* KPt = sm + 64*68;
    float* Vs  = sm + 64*68*2;

    int bx = blockIdx.x;
    int qt = bx & 15, h = (bx >> 4) & 7, b = bx >> 7;
    int len = lengths[b];
    int tid = threadIdx.x;
    int ty = tid >> 4, tx = tid & 15;

    // Load Q tile (pre-scaled by HS^-0.5), transposed: Qt[e][i]
    for (int idx = tid; idx < 4096; idx += 256){
        int i = idx >> 6, e = idx & 63;
        int t = qt*64 + i;
        Qt[e*68 + i] = qkv[(size_t)(b*TT + t)*QKVN + h*64 + e] * 0.125f;
    }

    float acc[4][4] = {};
    float m[4]    = {-1e30f,-1e30f,-1e30f,-1e30f};
    float lsum[4] = {0.f,0.f,0.f,0.f};

    for (int s0 = 0; s0 < TT; s0 += 64){
        if (s0 >= len) break;
        __syncthreads();                       // prior-iter reads of KPt/Vs done
        for (int idx = tid; idx < 4096; idx += 256){
            int j = idx >> 6, e = idx & 63;
            size_t base = (size_t)(b*TT + s0 + j)*QKVN + h*64 + e;
            KPt[e*68 + j] = qkv[base + 512];   // K transposed
            Vs[j*64 + e]  = qkv[base + 1024];  // V natural
        }
        __syncthreads();

        // S = Q K^T (regs, 4x4 per thread)
        float s[4][4] = {};
#pragma unroll
        for (int e=0; e<64; e++){
            float a0=Qt[e*68+(ty<<2)+0], a1=Qt[e*68+(ty<<2)+1],
                  a2=Qt[e*68+(ty<<2)+2], a3=Qt[e*68+(ty<<2)+3];
            float b0=KPt[e*68+(tx<<2)+0], b1=KPt[e*68+(tx<<2)+1],
                  b2=KPt[e*68+(tx<<2)+2], b3=KPt[e*68+(tx<<2)+3];
            s[0][0]+=a0*b0; s[0][1]+=a0*b1; s[0][2]+=a0*b2; s[0][3]+=a0*b3;
            s[1][0]+=a1*b0; s[1][1]+=a1*b1; s[1][2]+=a1*b2; s[1][3]+=a1*b3;
            s[2][0]+=a2*b0; s[2][1]+=a2*b1; s[2][2]+=a2*b2; s[2][3]+=a2*b3;
            s[3][0]+=a3*b0; s[3][1]+=a3*b1; s[3][2]+=a3*b2; s[3][3]+=a3*b3;
        }
        // column mask
#pragma unroll
        for (int j=0;j<4;j++){
            if (s0 + (tx<<2) + j >= len){
#pragma unroll
                for (int i=0;i<4;i++) s[i][j] = -1e30f;
            }
        }
        // online softmax per row (row group = 16 consecutive lanes)
#pragma unroll
        for (int i=0;i<4;i++){
            float mx = fmaxf(fmaxf(s[i][0],s[i][1]), fmaxf(s[i][2],s[i][3]));
#pragma unroll
            for (int o=8;o;o>>=1) mx = fmaxf(mx, __shfl_xor_sync(0xffffffffu, mx, o));
            float mnew = fmaxf(m[i], mx);
            float corr = __expf(m[i] - mnew);
            float rs = 0.f;
#pragma unroll
            for (int j=0;j<4;j++){
                float p = __expf(s[i][j] - mnew);
                s[i][j] = p;
                rs += p;
            }
#pragma unroll
            for (int o=8;o;o>>=1) rs += __shfl_xor_sync(0xffffffffu, rs, o);
            lsum[i] = lsum[i]*corr + rs;
            m[i] = mnew;
#pragma unroll
            for (int j=0;j<4;j++) acc[i][j] *= corr;
        }
        __syncthreads();                       // all done reading KPt as K
        // write P into KPt buffer: P[row][j] (stride 68)
#pragma unroll
        for (int i=0;i<4;i++)
#pragma unroll
            for (int j=0;j<4;j++)
                KPt[((ty<<2)+i)*68 + (tx<<2)+j] = s[i][j];
        __syncthreads();
        // O += P @ V
#pragma unroll
        for (int j=0;j<64;j++){
            float p0=KPt[((ty<<2)+0)*68 + j], p1=KPt[((ty<<2)+1)*68 + j],
                  p2=KPt[((ty<<2)+2)*68 + j], p3=KPt[((ty<<2)+3)*68 + j];
            float v0=Vs[j*64+(tx<<2)+0], v1=Vs[j*64+(tx<<2)+1],
                  v2=Vs[j*64+(tx<<2)+2], v3=Vs[j*64+(tx<<2)+3];
            acc[0][0]+=p0*v0; acc[0][1]+=p0*v1; acc[0][2]+=p0*v2; acc[0][3]+=p0*v3;
            acc[1][0]+=p1*v0; acc[1][1]+=p1*v1; acc[1][2]+=p1*v2; acc[1][3]+=p1*v3;
            acc[2][0]+=p2*v0; acc[2][1]+=p2*v1; acc[2][2]+=p2*v2; acc[2][3]+=p2*v3;
            acc[3][0]+=p3*v0; acc[3][1]+=p3*v1; acc[3][2]+=p3*v2; acc[3][3]+=p3*v3;
        }
    }
    // write out (row-masked queries -> 0)
#pragma unroll
    for (int i=0;i<4;i++){
        int t = qt*64 + (ty<<2) + i;
        float invl = (t < len) ? (1.0f/lsum[i]) : 0.0f;
#pragma unroll
        for (int j=0;j<4;j++)
            ao[(size_t)(b*TT + t)*DD + h*64 + (tx<<2) + j] = acc[i][j]*invl;
    }
}

// ---------------- attention-pool head ----------------
__global__ void score_kernel(const float* __restrict__ xn, const float* __restrict__ attn_w,
                             const float* __restrict__ attn_b, float* __restrict__ scores){
    __shared__ float sh[32];
    int row = blockIdx.x;
    float s = 0.f;
    for (int d = threadIdx.x; d < DD; d += blockDim.x)
        s += xn[(size_t)row*DD + d] * attn_w[d];
    s = block_sum(s, sh);
    if (threadIdx.x == 0) scores[row] = s + attn_b[0];
}

__global__ void pool_kernel(const float* __restrict__ scores, const int* __restrict__ lengths,
                            const float* __restrict__ xn, float* __restrict__ summary){
    __shared__ float aw[TT];
    __shared__ float sh[32];
    int b = blockIdx.x;
    int len = lengths[b];
    int tid = threadIdx.x;
    float mx = -3.0e38f;
    for (int t = tid; t < TT; t += blockDim.x){
        float s = (t < len) ? scores[b*TT + t] : -3.0e38f;
        aw[t] = s;
        mx = fmaxf(mx, s);
    }
    mx = block_max(mx, sh);
    float ssum = 0.f;
    for (int t = tid; t < TT; t += blockDim.x){
        float e = (t < len) ? __expf(aw[t] - mx) : 0.f;
        aw[t] = e;
        ssum += e;
    }
    ssum = block_sum(ssum, sh);
    __syncthreads();
    float inv = 1.0f / ssum;
    for (int d = tid; d < DD; d += blockDim.x){
        float acc = 0.f;
        for (int t = 0; t < TT; t++)
            acc += aw[t] * xn[(size_t)(b*TT + t)*DD + d];
        summary[b*DD + d] = acc * inv;
    }
}

__global__ void head_kernel(const float* __restrict__ summary, const float* __restrict__ head_w,
                            const float* __restrict__ head_b, float* __restrict__ out){
    int tid = threadIdx.x;
    if (tid >= BB*49) return;
    int b = tid / 49, o = tid % 49;
    float a = head_b[o];
    for (int d = 0; d < DD; d++)
        a += summary[b*DD + d] * head_w[d*49 + o];
    out[tid] = a;
}

// ---------------- host orchestration ----------------
extern "C" void kernel_launch(void* const* d_in, const int* in_sizes, int n_in,
                              void* d_out, int out_size){
    (void)in_sizes; (void)n_in; (void)out_size;
    const int*   code    = (const int*)  d_in[0];
    const int*   lengths = (const int*)  d_in[1];
    const float* emb     = (const float*)d_in[2];
    const float* Wq      = (const float*)d_in[3];
    const float* Wk      = (const float*)d_in[4];
    const float* Wv      = (const float*)d_in[5];
    const float* Wo      = (const float*)d_in[6];
    const float* bo      = (const float*)d_in[7];
    const float* W1      = (const float*)d_in[8];
    const float* b1      = (const float*)d_in[9];
    const float* W2      = (const float*)d_in[10];
    const float* b2      = (const float*)d_in[11];
    const float* ln1_g   = (const float*)d_in[12];
    const float* ln1_b   = (const float*)d_in[13];
    const float* ln2_g   = (const float*)d_in[14];
    const float* ln2_b   = (const float*)d_in[15];
    const float* lnf_g   = (const float*)d_in[16];
    const float* lnf_b   = (const float*)d_in[17];
    const float* attn_w  = (const float*)d_in[18];
    const float* attn_b  = (const float*)d_in[19];
    const float* head_w  = (const float*)d_in[20];
    const float* head_b  = (const float*)d_in[21];

    float *x, *xn, *qkv, *ao, *h1, *wt, *scores, *summary;
    cudaGetSymbolAddress((void**)&x,       g_x);
    cudaGetSymbolAddress((void**)&xn,      g_xn);
    cudaGetSymbolAddress((void**)&qkv,     g_qkv);
    cudaGetSymbolAddress((void**)&ao,      g_ao);
    cudaGetSymbolAddress((void**)&h1,      g_h1);
    cudaGetSymbolAddress((void**)&wt,      g_wt);
    cudaGetSymbolAddress((void**)&scores,  g_scores);
    cudaGetSymbolAddress((void**)&summary, g_summary);

    cudaFuncSetAttribute(attn_kernel, cudaFuncAttributeMaxDynamicSharedMemorySize, ATT_SMEM);

    embed_kernel<<<(NT*DD + 255)/256, 256>>>(code, emb, x);

    for (int l = 0; l < LL; l++){
        ln_kernel<<<NT, 256>>>(x, ln1_g + l*DD, ln1_b + l*DD, xn);
        wqkv_t_kernel<<<(DD*QKVN + 255)/256, 256>>>(Wq, Wk, Wv, wt, l);
        sgemm_kernel<<<dim3(QKVN/BN, NT/BM), 256>>>(xn, wt, qkv, nullptr, nullptr,
                                                    NT, QKVN, DD, 0);
        attn_kernel<<<BB*HH*(TT/64), 256, ATT_SMEM>>>(qkv, lengths, ao);
        sgemm_kernel<<<dim3(DD/BN, NT/BM), 256>>>(ao, Wo + (size_t)l*DD*DD, x,
                                                  bo + l*DD, x, NT, DD, DD, 1|4);
        ln_kernel<<<NT, 256>>>(x, ln2_g + l*DD, ln2_b + l*DD, xn);
        sgemm_kernel<<<dim3(DFF/BN, NT/BM), 256>>>(xn, W1 + (size_t)l*DD*DFF, h1,
                                                   b1 + l*DFF, nullptr, NT, DFF, DD, 1|2);
        sgemm_kernel<<<dim3(DD/BN, NT/BM), 256>>>(h1, W2 + (size_t)l*DFF*DD, x,
                                                  b2 + l*DD, x, NT, DD, DFF, 1|4);
    }

    ln_kernel<<<NT, 256>>>(x, lnf_g, lnf_b, xn);
    score_kernel<<<NT, 128>>>(xn, attn_w, attn_b, scores);
    pool_kernel<<<BB, 256>>>(scores, lengths, xn, summary);
    head_kernel<<<1, 512>>>(summary, head_w, head_b, (float*)d_out);
}

// round 9
// speedup vs baseline: 1.6468x; 1.6468x over previous
#include <cuda_runtime.h>
#include <cuda_bf16.h>
#include <math.h>
#include <stdint.h>

// ---------------- problem constants ----------------
#define BB 8
#define TT 1024
#define FF 32
#define EE 16
#define DD 512
#define LL 6
#define HH 8
#define HS 64
#define DFF 2048
#define NT (BB*TT)          // 8192 token rows
#define QKVN (3*DD)         // 1536

// ---------------- scratch (device globals; no allocs allowed) ----------------
__device__ float g_x[NT*DD];
__device__ float g_xn[NT*DD];           // final-LN fp32 output
__device__ float g_qkv[NT*QKVN];
__device__ float g_scores[NT];
__device__ float g_summary[BB*DD];
// bf16 hi/lo activation splits
__device__ __nv_bfloat16 g_xn_hi[NT*DD],  g_xn_lo[NT*DD];
__device__ __nv_bfloat16 g_ao_hi[NT*DD],  g_ao_lo[NT*DD];
__device__ __nv_bfloat16 g_h1_hi[NT*DFF], g_h1_lo[NT*DFF];
// bf16 hi/lo transposed weight splits (B^T layout: [N rows][K cols], K-major)
__device__ __nv_bfloat16 g_wqkv_hi[LL*QKVN*DD], g_wqkv_lo[LL*QKVN*DD];
__device__ __nv_bfloat16 g_wo_hi[LL*DD*DD],     g_wo_lo[LL*DD*DD];
__device__ __nv_bfloat16 g_w1_hi[LL*DFF*DD],    g_w1_lo[LL*DFF*DD];
__device__ __nv_bfloat16 g_w2_hi[LL*DD*DFF],    g_w2_lo[LL*DD*DFF];

// ---------------- PTX helpers (baseline sm_80-class features only) ----------------
__device__ __forceinline__ uint32_t smem_u32(const void* p){
    uint32_t a;
    asm("{ .reg .u64 t; cvta.to.shared.u64 t, %1; cvt.u32.u64 %0, t; }" : "=r"(a) : "l"(p));
    return a;
}
#define SW128(o) ((o) ^ (((o)>>3)&0x70))

__device__ __forceinline__ void cp16(uint32_t saddr, const void* g){
    asm volatile("cp.async.ca.shared.global [%0], [%1], 16;" :: "r"(saddr), "l"(g));
}
#define CP_COMMIT()  asm volatile("cp.async.commit_group;" ::: "memory")
#define CP_WAIT1()   asm volatile("cp.async.wait_group 1;" ::: "memory")
#define CP_WAIT0()   asm volatile("cp.async.wait_group 0;" ::: "memory")

#define LDSM4(r, addr) \
    asm volatile("ldmatrix.sync.aligned.m8n8.x4.shared.b16 {%0,%1,%2,%3}, [%4];" \
        : "=r"((r)[0]), "=r"((r)[1]), "=r"((r)[2]), "=r"((r)[3]) : "r"(addr))
#define LDSM2(r, addr) \
    asm volatile("ldmatrix.sync.aligned.m8n8.x2.shared.b16 {%0,%1}, [%2];" \
        : "=r"((r)[0]), "=r"((r)[1]) : "r"(addr))

#define MMA_BF16(d, a, b) \
    asm volatile("mma.sync.aligned.m16n8k16.row.col.f32.bf16.bf16.f32 " \
        "{%0,%1,%2,%3}, {%4,%5,%6,%7}, {%8,%9}, {%0,%1,%2,%3};" \
        : "+f"((d)[0]), "+f"((d)[1]), "+f"((d)[2]), "+f"((d)[3]) \
        : "r"((a)[0]), "r"((a)[1]), "r"((a)[2]), "r"((a)[3]), \
          "r"((b)[0]), "r"((b)[1]))

// ---------------- reductions ----------------
__device__ __forceinline__ float warp_sum(float v){
#pragma unroll
    for (int o=16;o;o>>=1) v += __shfl_xor_sync(0xffffffffu, v, o);
    return v;
}
__device__ __forceinline__ float warp_max(float v){
#pragma unroll
    for (int o=16;o;o>>=1) v = fmaxf(v, __shfl_xor_sync(0xffffffffu, v, o));
    return v;
}
__device__ float block_sum(float v, float* sh){
    int lane = threadIdx.x & 31, w = threadIdx.x >> 5;
    v = warp_sum(v);
    if (lane==0) sh[w] = v;
    __syncthreads();
    int nw = (blockDim.x + 31) >> 5;
    float r = (threadIdx.x < nw) ? sh[threadIdx.x] : 0.f;
    r = warp_sum(r);
    if (threadIdx.x==0) sh[0] = r;
    __syncthreads();
    r = sh[0];
    __syncthreads();
    return r;
}
__device__ float block_max(float v, float* sh){
    int lane = threadIdx.x & 31, w = threadIdx.x >> 5;
    v = warp_max(v);
    if (lane==0) sh[w] = v;
    __syncthreads();
    int nw = (blockDim.x + 31) >> 5;
    float r = (threadIdx.x < nw) ? sh[threadIdx.x] : -3.0e38f;
    r = warp_max(r);
    if (threadIdx.x==0) sh[0] = r;
    __syncthreads();
    r = sh[0];
    __syncthreads();
    return r;
}

// ---------------- embedding + positional encoding ----------------
__global__ void embed_kernel(const int* __restrict__ code, const float* __restrict__ emb,
                             float* __restrict__ x){
    int idx = blockIdx.x*blockDim.x + threadIdx.x;
    if (idx >= NT*DD) return;
    int d  = idx % DD;
    int bt = idx / DD;
    int t  = bt % TT;
    int f  = d / EE, e = d % EE;
    int c  = code[bt*FF + f];
    float i2  = (float)((d >> 1) << 1);
    float div = __expf(i2 * (-9.210340371976184f / (float)DD));   // -ln(10000)/D
    float ang = (float)t * div;
    float pe  = (d & 1) ? cosf(ang) : sinf(ang);
    x[idx] = emb[c*EE + e] + pe;
}

// ---------------- LayerNorm: mode bit0 write fp32, bit1 write bf16 hi/lo ----------------
__global__ void ln_kernel(const float* __restrict__ x, const float* __restrict__ g,
                          const float* __restrict__ b, float* __restrict__ y,
                          __nv_bfloat16* __restrict__ yhi, __nv_bfloat16* __restrict__ ylo,
                          int mode){
    __shared__ float sh[32];
    int row = blockIdx.x;
    int tid = threadIdx.x;                     // 256 threads, D=512
    const float* xr = x + (size_t)row*DD;
    float v0 = xr[tid], v1 = xr[tid+256];
    float mean = block_sum(v0+v1, sh) * (1.0f/DD);
    float d0 = v0-mean, d1 = v1-mean;
    float var = block_sum(d0*d0 + d1*d1, sh) * (1.0f/DD);
    float inv = rsqrtf(var + 1e-5f);
    float r0 = d0*inv*g[tid]     + b[tid];
    float r1 = d1*inv*g[tid+256] + b[tid+256];
    size_t o0 = (size_t)row*DD + tid, o1 = o0 + 256;
    if (mode & 1){ y[o0] = r0; y[o1] = r1; }
    if (mode & 2){
        __nv_bfloat16 h0 = __float2bfloat16(r0), h1 = __float2bfloat16(r1);
        yhi[o0] = h0; yhi[o1] = h1;
        ylo[o0] = __float2bfloat16(r0 - __bfloat162float(h0));
        ylo[o1] = __float2bfloat16(r1 - __bfloat162float(h1));
    }
}

// ---------------- weight prep: QKV pack (B^T layout [1536][512]) + split ----------------
__global__ void wqkv_prep(const float* __restrict__ Wq, const float* __restrict__ Wk,
                          const float* __restrict__ Wv,
                          __nv_bfloat16* __restrict__ hi, __nv_bfloat16* __restrict__ lo){
    size_t idx = (size_t)blockIdx.x*256 + threadIdx.x;
    if (idx >= (size_t)LL*QKVN*DD) return;
    int d = (int)(idx % DD);
    size_t r = idx / DD;
    int j = (int)(r % QKVN);
    int l = (int)(r / QKVN);
    int sel = j >> 9, h = (j >> 6) & 7, e = j & 63;
    const float* W = (sel==0) ? Wq : (sel==1) ? Wk : Wv;
    float v = W[(((size_t)l*HH + h)*DD + d)*HS + e];
    __nv_bfloat16 hb = __float2bfloat16(v);
    hi[idx] = hb;
    lo[idx] = __float2bfloat16(v - __bfloat162float(hb));
}

// ---------------- weight prep: tiled transpose + split (W[K,N] -> Bt[N,K]) ----------------
__global__ void tsplit_kernel(const float* __restrict__ W, __nv_bfloat16* __restrict__ hi,
                              __nv_bfloat16* __restrict__ lo, int K, int N){
    __shared__ float t[32][33];
    int n0 = blockIdx.x*32, k0 = blockIdx.y*32;
    int tx = threadIdx.x, ty = threadIdx.y;    // block (32,8)
#pragma unroll
    for (int i=0;i<32;i+=8)
        t[ty+i][tx] = W[(size_t)(k0+ty+i)*N + n0 + tx];
    __syncthreads();
#pragma unroll
    for (int i=0;i<32;i+=8){
        float v = t[tx][ty+i];
        size_t o = (size_t)(n0+ty+i)*K + k0 + tx;
        __nv_bfloat16 h = __float2bfloat16(v);
        hi[o] = h;
        lo[o] = __float2bfloat16(v - __bfloat162float(h));
    }
}

// ---------------- bf16-split tensor-core GEMM (mma.sync path) ----------------
// C[M,N] = (Ah+Al)[M,K] @ (Bh+Bl)^T  where Bt is [N,K] K-major.
// 3-term split: Ah*Bh + Al*Bh + Ah*Bl  (error ~2^-16).
// 128x128 CTA tile, 8 warps (2x4 grid of 64x32 warp tiles), BK=64,
// SW128-swizzled smem, cp.async double buffering.
// epi: 1 +bias[col]; 2 GELU; 4 +res; 8 write fp32 C; 16 write bf16 hi/lo split.
#define TILE_B 16384                         // bytes per 128x64 bf16 tile
#define BUF_B  (4*TILE_B)                    // Ah|Al|Bh|Bl per buffer
#define GEMM_SMEM (2*BUF_B)                  // 131072 B

__device__ __forceinline__ void load_tile_async(uint32_t sbase,
        const __nv_bfloat16* __restrict__ src, int ldK, int k0, int tid){
#pragma unroll
    for (int it=0; it<4; it++){
        int idx = tid + it*256;
        int r = idx >> 3, q = idx & 7;
        cp16(sbase + (uint32_t)SW128(r*128 + q*16),
             src + (size_t)r*ldK + k0 + q*8);
    }
}

__global__ void __launch_bounds__(256)
tc_gemm(const __nv_bfloat16* __restrict__ Ah, const __nv_bfloat16* __restrict__ Al,
        const __nv_bfloat16* __restrict__ Bh, const __nv_bfloat16* __restrict__ Bl,
        float* __restrict__ C, const float* __restrict__ bias,
        const float* __restrict__ res,
        __nv_bfloat16* __restrict__ Ohi, __nv_bfloat16* __restrict__ Olo,
        int N, int K, int epi){
    extern __shared__ char sm[];
    uint32_t smb = smem_u32(sm);
    int tid = threadIdx.x;
    int wid = tid >> 5, lane = tid & 31;
    int warp_m = wid >> 2, warp_n = wid & 3;       // 2 x 4 warp grid
    int row0 = blockIdx.y*128, col0 = blockIdx.x*128;

    const __nv_bfloat16* Abh = Ah + (size_t)row0*K;
    const __nv_bfloat16* Abl = Al + (size_t)row0*K;
    const __nv_bfloat16* Bbh = Bh + (size_t)col0*K;
    const __nv_bfloat16* Bbl = Bl + (size_t)col0*K;
    int chunks = K >> 6;

    // prologue: chunk 0 -> buffer 0
    load_tile_async(smb,            Abh, K, 0, tid);
    load_tile_async(smb +   TILE_B, Abl, K, 0, tid);
    load_tile_async(smb + 2*TILE_B, Bbh, K, 0, tid);
    load_tile_async(smb + 3*TILE_B, Bbl, K, 0, tid);
    CP_COMMIT();

    float acc[4][4][4] = {};
    // ldmatrix lane addressing
    int aRow = warp_m*64 + (lane & 15);            // + i*16
    int aKof = (lane >> 4) << 4;                   // 0 or 16 bytes
    int bRow = warp_n*32 + (lane & 7);             // + j*8
    int bKof = ((lane >> 3) & 1) << 4;

    for (int c = 0; c < chunks; c++){
        if (c+1 < chunks){
            uint32_t nb = smb + (uint32_t)((c+1)&1)*BUF_B;
            int k0 = (c+1) << 6;
            load_tile_async(nb,            Abh, K, k0, tid);
            load_tile_async(nb +   TILE_B, Abl, K, k0, tid);
            load_tile_async(nb + 2*TILE_B, Bbh, K, k0, tid);
            load_tile_async(nb + 3*TILE_B, Bbl, K, k0, tid);
            CP_COMMIT();
            CP_WAIT1();
        } else {
            CP_WAIT0();
        }
        __syncthreads();                           // chunk c visible to all

        uint32_t bA_h = smb + (uint32_t)(c&1)*BUF_B;
        uint32_t bA_l = bA_h + TILE_B;
        uint32_t bB_h = bA_h + 2*TILE_B;
        uint32_t bB_l = bA_h + 3*TILE_B;

#pragma unroll
        for (int ks = 0; ks < 4; ks++){
            int kb = ks*32;
            uint32_t ah[4][4], al[4][4], bh[4][2], bl[4][2];
#pragma unroll
            for (int i=0;i<4;i++){
                uint32_t off = (uint32_t)SW128((aRow + i*16)*128 + kb + aKof);
                LDSM4(ah[i], bA_h + off);
                LDSM4(al[i], bA_l + off);
            }
#pragma unroll
            for (int j=0;j<4;j++){
                uint32_t off = (uint32_t)SW128((bRow + j*8)*128 + kb + bKof);
                LDSM2(bh[j], bB_h + off);
                LDSM2(bl[j], bB_l + off);
            }
#pragma unroll
            for (int i=0;i<4;i++)
#pragma unroll
                for (int j=0;j<4;j++){
                    MMA_BF16(acc[i][j], ah[i], bh[j]);
                    MMA_BF16(acc[i][j], al[i], bh[j]);
                    MMA_BF16(acc[i][j], ah[i], bl[j]);
                }
        }
        __syncthreads();                           // done reading buf c&1
    }

    // ---------------- epilogue on mma fragments ----------------
    int gRow = lane >> 2;
    int colq = (lane & 3) << 1;
#pragma unroll
    for (int i=0;i<4;i++){
        int rA = row0 + warp_m*64 + i*16 + gRow;
#pragma unroll
        for (int half=0; half<2; half++){
            int r = rA + half*8;
#pragma unroll
            for (int j=0;j<4;j++){
                int cB = col0 + warp_n*32 + j*8 + colq;
                float v0 = acc[i][j][2*half+0];
                float v1 = acc[i][j][2*half+1];
                if (epi & 1){ v0 += bias[cB]; v1 += bias[cB+1]; }
                if (epi & 2){
                    v0 = 0.5f*v0*(1.0f + erff(v0*0.70710678118654752f));
                    v1 = 0.5f*v1*(1.0f + erff(v1*0.70710678118654752f));
                }
                if (epi & 4){
                    float2 rv = *(const float2*)&res[(size_t)r*N + cB];
                    v0 += rv.x; v1 += rv.y;
                }
                if (epi & 8)
                    *(float2*)&C[(size_t)r*N + cB] = make_float2(v0, v1);
                if (epi & 16){
                    __nv_bfloat16 h0 = __float2bfloat16(v0);
                    __nv_bfloat16 h1 = __float2bfloat16(v1);
                    __nv_bfloat16 l0 = __float2bfloat16(v0 - __bfloat162float(h0));
                    __nv_bfloat16 l1 = __float2bfloat16(v1 - __bfloat162float(h1));
                    *(__nv_bfloat162*)&Ohi[(size_t)r*N + cB] = __halves2bfloat162(h0, h1);
                    *(__nv_bfloat162*)&Olo[(size_t)r*N + cB] = __halves2bfloat162(l0, l1);
                }
            }
        }
    }
}

// ---------------- flash attention: CTA per (b, h, 64-query tile) ----------------
// dynamic smem layout: Qt[64*68] | KPt[64*68] (K tile, reused for P) | Vs[64*64]
#define ATT_SMEM ((64*68*2 + 64*64)*4)
__global__ void __launch_bounds__(256)
attn_kernel(const float* __restrict__ qkv, const int* __restrict__ lengths,
            __nv_bfloat16* __restrict__ ao_hi, __nv_bfloat16* __restrict__ ao_lo){
    extern __shared__ float smf[];
    float* Qt  = smf;
    float* KPt = smf + 64*68;
    float* Vs  = smf + 64*68*2;

    int bx = blockIdx.x;
    int qt = bx & 15, h = (bx >> 4) & 7, b = bx >> 7;
    int len = lengths[b];
    int tid = threadIdx.x;
    int ty = tid >> 4, tx = tid & 15;

    for (int idx = tid; idx < 4096; idx += 256){
        int i = idx >> 6, e = idx & 63;
        int t = qt*64 + i;
        Qt[e*68 + i] = qkv[(size_t)(b*TT + t)*QKVN + h*64 + e] * 0.125f;
    }

    float acc[4][4] = {};
    float m[4]    = {-1e30f,-1e30f,-1e30f,-1e30f};
    float lsum[4] = {0.f,0.f,0.f,0.f};

    for (int s0 = 0; s0 < TT; s0 += 64){
        if (s0 >= len) break;
        __syncthreads();
        for (int idx = tid; idx < 4096; idx += 256){
            int j = idx >> 6, e = idx & 63;
            size_t base = (size_t)(b*TT + s0 + j)*QKVN + h*64 + e;
            KPt[e*68 + j] = qkv[base + 512];
            Vs[j*64 + e]  = qkv[base + 1024];
        }
        __syncthreads();

        float s[4][4] = {};
#pragma unroll
        for (int e=0; e<64; e++){
            float a0=Qt[e*68+(ty<<2)+0], a1=Qt[e*68+(ty<<2)+1],
                  a2=Qt[e*68+(ty<<2)+2], a3=Qt[e*68+(ty<<2)+3];
            float b0=KPt[e*68+(tx<<2)+0], b1=KPt[e*68+(tx<<2)+1],
                  b2=KPt[e*68+(tx<<2)+2], b3=KPt[e*68+(tx<<2)+3];
            s[0][0]+=a0*b0; s[0][1]+=a0*b1; s[0][2]+=a0*b2; s[0][3]+=a0*b3;
            s[1][0]+=a1*b0; s[1][1]+=a1*b1; s[1][2]+=a1*b2; s[1][3]+=a1*b3;
            s[2][0]+=a2*b0; s[2][1]+=a2*b1; s[2][2]+=a2*b2; s[2][3]+=a2*b3;
            s[3][0]+=a3*b0; s[3][1]+=a3*b1; s[3][2]+=a3*b2; s[3][3]+=a3*b3;
        }
#pragma unroll
        for (int j=0;j<4;j++){
            if (s0 + (tx<<2) + j >= len){
#pragma unroll
                for (int i=0;i<4;i++) s[i][j] = -1e30f;
            }
        }
#pragma unroll
        for (int i=0;i<4;i++){
            float mx = fmaxf(fmaxf(s[i][0],s[i][1]), fmaxf(s[i][2],s[i][3]));
#pragma unroll
            for (int o=8;o;o>>=1) mx = fmaxf(mx, __shfl_xor_sync(0xffffffffu, mx, o));
            float mnew = fmaxf(m[i], mx);
            float corr = __expf(m[i] - mnew);
            float rs = 0.f;
#pragma unroll
            for (int j=0;j<4;j++){
                float p = __expf(s[i][j] - mnew);
                s[i][j] = p;
                rs += p;
            }
#pragma unroll
            for (int o=8;o;o>>=1) rs += __shfl_xor_sync(0xffffffffu, rs, o);
            lsum[i] = lsum[i]*corr + rs;
            m[i] = mnew;
#pragma unroll
            for (int j=0;j<4;j++) acc[i][j] *= corr;
        }
        __syncthreads();
#pragma unroll
        for (int i=0;i<4;i++)
#pragma unroll
            for (int j=0;j<4;j++)
                KPt[((ty<<2)+i)*68 + (tx<<2)+j] = s[i][j];
        __syncthreads();
#pragma unroll
        for (int j=0;j<64;j++){
            float p0=KPt[((ty<<2)+0)*68 + j], p1=KPt[((ty<<2)+1)*68 + j],
                  p2=KPt[((ty<<2)+2)*68 + j], p3=KPt[((ty<<2)+3)*68 + j];
            float v0=Vs[j*64+(tx<<2)+0], v1=Vs[j*64+(tx<<2)+1],
                  v2=Vs[j*64+(tx<<2)+2], v3=Vs[j*64+(tx<<2)+3];
            acc[0][0]+=p0*v0; acc[0][1]+=p0*v1; acc[0][2]+=p0*v2; acc[0][3]+=p0*v3;
            acc[1][0]+=p1*v0; acc[1][1]+=p1*v1; acc[1][2]+=p1*v2; acc[1][3]+=p1*v3;
            acc[2][0]+=p2*v0; acc[2][1]+=p2*v1; acc[2][2]+=p2*v2; acc[2][3]+=p2*v3;
            acc[3][0]+=p3*v0; acc[3][1]+=p3*v1; acc[3][2]+=p3*v2; acc[3][3]+=p3*v3;
        }
    }
#pragma unroll
    for (int i=0;i<4;i++){
        int t = qt*64 + (ty<<2) + i;
        float invl = (t < len) ? (1.0f/lsum[i]) : 0.0f;
#pragma unroll
        for (int j=0;j<4;j++){
            float val = acc[i][j]*invl;
            size_t off = (size_t)(b*TT + t)*DD + h*64 + (tx<<2) + j;
            __nv_bfloat16 hb = __float2bfloat16(val);
            ao_hi[off] = hb;
            ao_lo[off] = __float2bfloat16(val - __bfloat162float(hb));
        }
    }
}

// ---------------- attention-pool head ----------------
__global__ void score_kernel(const float* __restrict__ xn, const float* __restrict__ attn_w,
                             const float* __restrict__ attn_b, float* __restrict__ scores){
    __shared__ float sh[32];
    int row = blockIdx.x;
    float s = 0.f;
    for (int d = threadIdx.x; d < DD; d += blockDim.x)
        s += xn[(size_t)row*DD + d] * attn_w[d];
    s = block_sum(s, sh);
    if (threadIdx.x == 0) scores[row] = s + attn_b[0];
}

__global__ void pool_kernel(const float* __restrict__ scores, const int* __restrict__ lengths,
                            const float* __restrict__ xn, float* __restrict__ summary){
    __shared__ float aw[TT];
    __shared__ float sh[32];
    int b = blockIdx.x;
    int len = lengths[b];
    int tid = threadIdx.x;
    float mx = -3.0e38f;
    for (int t = tid; t < TT; t += blockDim.x){
        float s = (t < len) ? scores[b*TT + t] : -3.0e38f;
        aw[t] = s;
        mx = fmaxf(mx, s);
    }
    mx = block_max(mx, sh);
    float ssum = 0.f;
    for (int t = tid; t < TT; t += blockDim.x){
        float e = (t < len) ? __expf(aw[t] - mx) : 0.f;
        aw[t] = e;
        ssum += e;
    }
    ssum = block_sum(ssum, sh);
    __syncthreads();
    float inv = 1.0f / ssum;
    for (int d = tid; d < DD; d += blockDim.x){
        float acc = 0.f;
        for (int t = 0; t < TT; t++)
            acc += aw[t] * xn[(size_t)(b*TT + t)*DD + d];
        summary[b*DD + d] = acc * inv;
    }
}

__global__ void head_kernel(const float* __restrict__ summary, const float* __restrict__ head_w,
                            const float* __restrict__ head_b, float* __restrict__ out){
    int tid = threadIdx.x;
    if (tid >= BB*49) return;
    int b = tid / 49, o = tid % 49;
    float a = head_b[o];
    for (int d = 0; d < DD; d++)
        a += summary[b*DD + d] * head_w[d*49 + o];
    out[tid] = a;
}

// ---------------- host orchestration ----------------
extern "C" void kernel_launch(void* const* d_in, const int* in_sizes, int n_in,
                              void* d_out, int out_size){
    (void)in_sizes; (void)n_in; (void)out_size;
    const int*   code    = (const int*)  d_in[0];
    const int*   lengths = (const int*)  d_in[1];
    const float* emb     = (const float*)d_in[2];
    const float* Wq      = (const float*)d_in[3];
    const float* Wk      = (const float*)d_in[4];
    const float* Wv      = (const float*)d_in[5];
    const float* Wo      = (const float*)d_in[6];
    const float* bo      = (const float*)d_in[7];
    const float* W1      = (const float*)d_in[8];
    const float* b1      = (const float*)d_in[9];
    const float* W2      = (const float*)d_in[10];
    const float* b2      = (const float*)d_in[11];
    const float* ln1_g   = (const float*)d_in[12];
    const float* ln1_b   = (const float*)d_in[13];
    const float* ln2_g   = (const float*)d_in[14];
    const float* ln2_b   = (const float*)d_in[15];
    const float* lnf_g   = (const float*)d_in[16];
    const float* lnf_b   = (const float*)d_in[17];
    const float* attn_w  = (const float*)d_in[18];
    const float* attn_b  = (const float*)d_in[19];
    const float* head_w  = (const float*)d_in[20];
    const float* head_b  = (const float*)d_in[21];

    float *x, *xn, *qkv, *scores, *summary;
    __nv_bfloat16 *xn_hi, *xn_lo, *ao_hi, *ao_lo, *h1_hi, *h1_lo;
    __nv_bfloat16 *wqkv_hi, *wqkv_lo, *wo_hi, *wo_lo, *w1_hi, *w1_lo, *w2_hi, *w2_lo;
    cudaGetSymbolAddress((void**)&x,       g_x);
    cudaGetSymbolAddress((void**)&xn,      g_xn);
    cudaGetSymbolAddress((void**)&qkv,     g_qkv);
    cudaGetSymbolAddress((void**)&scores,  g_scores);
    cudaGetSymbolAddress((void**)&summary, g_summary);
    cudaGetSymbolAddress((void**)&xn_hi,   g_xn_hi);
    cudaGetSymbolAddress((void**)&xn_lo,   g_xn_lo);
    cudaGetSymbolAddress((void**)&ao_hi,   g_ao_hi);
    cudaGetSymbolAddress((void**)&ao_lo,   g_ao_lo);
    cudaGetSymbolAddress((void**)&h1_hi,   g_h1_hi);
    cudaGetSymbolAddress((void**)&h1_lo,   g_h1_lo);
    cudaGetSymbolAddress((void**)&wqkv_hi, g_wqkv_hi);
    cudaGetSymbolAddress((void**)&wqkv_lo, g_wqkv_lo);
    cudaGetSymbolAddress((void**)&wo_hi,   g_wo_hi);
    cudaGetSymbolAddress((void**)&wo_lo,   g_wo_lo);
    cudaGetSymbolAddress((void**)&w1_hi,   g_w1_hi);
    cudaGetSymbolAddress((void**)&w1_lo,   g_w1_lo);
    cudaGetSymbolAddress((void**)&w2_hi,   g_w2_hi);
    cudaGetSymbolAddress((void**)&w2_lo,   g_w2_lo);

    cudaFuncSetAttribute(attn_kernel, cudaFuncAttributeMaxDynamicSharedMemorySize, ATT_SMEM);
    cudaFuncSetAttribute(tc_gemm, cudaFuncAttributeMaxDynamicSharedMemorySize, GEMM_SMEM);

    embed_kernel<<<(NT*DD + 255)/256, 256>>>(code, emb, x);

    // weight prep (all layers)
    {
        size_t tot = (size_t)LL*QKVN*DD;
        wqkv_prep<<<(unsigned)((tot + 255)/256), 256>>>(Wq, Wk, Wv, wqkv_hi, wqkv_lo);
        dim3 blk(32,8);
        for (int l = 0; l < LL; l++){
            tsplit_kernel<<<dim3(DD/32,  DD/32),  blk>>>(Wo + (size_t)l*DD*DD,
                    wo_hi + (size_t)l*DD*DD, wo_lo + (size_t)l*DD*DD, DD, DD);
            tsplit_kernel<<<dim3(DFF/32, DD/32),  blk>>>(W1 + (size_t)l*DD*DFF,
                    w1_hi + (size_t)l*DFF*DD, w1_lo + (size_t)l*DFF*DD, DD, DFF);
            tsplit_kernel<<<dim3(DD/32,  DFF/32), blk>>>(W2 + (size_t)l*DFF*DD,
                    w2_hi + (size_t)l*DD*DFF, w2_lo + (size_t)l*DD*DFF, DFF, DD);
        }
    }

    for (int l = 0; l < LL; l++){
        ln_kernel<<<NT, 256>>>(x, ln1_g + l*DD, ln1_b + l*DD, nullptr, xn_hi, xn_lo, 2);
        tc_gemm<<<dim3(QKVN/128, NT/128), 256, GEMM_SMEM>>>(
            xn_hi, xn_lo, wqkv_hi + (size_t)l*QKVN*DD, wqkv_lo + (size_t)l*QKVN*DD,
            qkv, nullptr, nullptr, nullptr, nullptr, QKVN, DD, 8);
        attn_kernel<<<BB*HH*(TT/64), 256, ATT_SMEM>>>(qkv, lengths, ao_hi, ao_lo);
        tc_gemm<<<dim3(DD/128, NT/128), 256, GEMM_SMEM>>>(
            ao_hi, ao_lo, wo_hi + (size_t)l*DD*DD, wo_lo + (size_t)l*DD*DD,
            x, bo + l*DD, x, nullptr, nullptr, DD, DD, 1|4|8);
        ln_kernel<<<NT, 256>>>(x, ln2_g + l*DD, ln2_b + l*DD, nullptr, xn_hi, xn_lo, 2);
        tc_gemm<<<dim3(DFF/128, NT/128), 256, GEMM_SMEM>>>(
            xn_hi, xn_lo, w1_hi + (size_t)l*DFF*DD, w1_lo + (size_t)l*DFF*DD,
            nullptr, b1 + l*DFF, nullptr, h1_hi, h1_lo, DFF, DD, 1|2|16);
        tc_gemm<<<dim3(DD/128, NT/128), 256, GEMM_SMEM>>>(
            h1_hi, h1_lo, w2_hi + (size_t)l*DD*DFF, w2_lo + (size_t)l*DD*DFF,
            x, b2 + l*DD, x, nullptr, nullptr, DD, DFF, 1|4|8);
    }

    ln_kernel<<<NT, 256>>>(x, lnf_g, lnf_b, xn, nullptr, nullptr, 1);
    score_kernel<<<NT, 128>>>(xn, attn_w, attn_b, scores);
    pool_kernel<<<BB, 256>>>(scores, lengths, xn, summary);
    head_kernel<<<1, 512>>>(summary, head_w, head_b, (float*)d_out);
}